// round 10
// baseline (speedup 1.0000x reference)
#include <cuda_runtime.h>
#include <cuda_fp16.h>

#define N_PTS 100000
#define C_IN 24
#define C_HID 144
#define C_OUT 24
#define KS 9
#define EPS 1e-5f

// ---- scratch (device globals: allocation-free rule) ----
__device__ __align__(16) __half g_x1h[(N_PTS + 1) * C_HID];
__device__ __align__(16) __half g_x2h[N_PTS * C_HID];
__device__ __align__(16) float  g_y [N_PTS * C_OUT];

__device__ float g_s1[C_HID], g_q1[C_HID];
__device__ float g_s2[C_HID], g_q2[C_HID];
__device__ float g_s3[C_OUT], g_q3[C_OUT];

__device__ __forceinline__ float relu6f(float x) { return fminf(fmaxf(x, 0.f), 6.f); }

__device__ __forceinline__ void mma16816(float* d,
                                         unsigned a0, unsigned a1, unsigned a2, unsigned a3,
                                         unsigned b0, unsigned b1) {
    asm volatile("mma.sync.aligned.m16n8k16.row.col.f32.f16.f16.f32 "
                 "{%0,%1,%2,%3}, {%4,%5,%6,%7}, {%8,%9}, {%0,%1,%2,%3};\n"
                 : "+f"(d[0]), "+f"(d[1]), "+f"(d[2]), "+f"(d[3])
                 : "r"(a0), "r"(a1), "r"(a2), "r"(a3), "r"(b0), "r"(b1));
}

// ---- K1: x1 = feats @ w1 (fp16 out, fp32 stats); block0 zeroes stage-2 accums ----
#define R1 64
#define T1 288
__global__ void __launch_bounds__(T1) k1_gemm1(const float* __restrict__ feats,
                                               const float* __restrict__ w1) {
    __shared__ __align__(16) float sfT[C_IN][R1];
    __shared__ __align__(16) float sw1[C_IN * C_HID];
    __shared__ __align__(16) float rs[8][C_HID], rq[8][C_HID];

    int tid = threadIdx.x;
    int row0 = blockIdx.x * R1;

    if (blockIdx.x == 0 && tid < C_HID) { g_s2[tid] = 0.f; g_q2[tid] = 0.f; }

    for (int i = tid; i < C_IN * C_HID; i += T1) sw1[i] = w1[i];
    for (int i = tid; i < R1 * C_IN; i += T1) {
        int r = i / C_IN, k = i % C_IN;
        int rr = row0 + r;
        sfT[k][r] = (rr < N_PTS) ? feats[rr * C_IN + k] : 0.f;
    }
    __syncthreads();

    int c4 = tid % 36, rg = tid / 36;
    int cb = c4 * 4;
    float4 acc[8];
#pragma unroll
    for (int j = 0; j < 8; j++) acc[j] = make_float4(0.f, 0.f, 0.f, 0.f);

#pragma unroll
    for (int k = 0; k < C_IN; k++) {
        float4 w  = *(const float4*)&sw1[k * C_HID + cb];
        float4 xa = *(const float4*)&sfT[k][rg * 8];
        float4 xb = *(const float4*)&sfT[k][rg * 8 + 4];
        float xr[8] = {xa.x, xa.y, xa.z, xa.w, xb.x, xb.y, xb.z, xb.w};
#pragma unroll
        for (int j = 0; j < 8; j++) {
            acc[j].x = fmaf(w.x, xr[j], acc[j].x);
            acc[j].y = fmaf(w.y, xr[j], acc[j].y);
            acc[j].z = fmaf(w.z, xr[j], acc[j].z);
            acc[j].w = fmaf(w.w, xr[j], acc[j].w);
        }
    }

    float4 s4 = make_float4(0.f, 0.f, 0.f, 0.f), q4 = s4;
#pragma unroll
    for (int j = 0; j < 8; j++) {
        int rr = row0 + rg * 8 + j;
        if (rr < N_PTS) {
            __half2 h0 = __floats2half2_rn(acc[j].x, acc[j].y);
            __half2 h1 = __floats2half2_rn(acc[j].z, acc[j].w);
            uint2 pk;
            pk.x = *(unsigned int*)&h0;
            pk.y = *(unsigned int*)&h1;
            *(uint2*)&g_x1h[(size_t)rr * C_HID + cb] = pk;
        }
        s4.x += acc[j].x; s4.y += acc[j].y; s4.z += acc[j].z; s4.w += acc[j].w;
        q4.x += acc[j].x * acc[j].x; q4.y += acc[j].y * acc[j].y;
        q4.z += acc[j].z * acc[j].z; q4.w += acc[j].w * acc[j].w;
    }
    *(float4*)&rs[rg][cb] = s4;
    *(float4*)&rq[rg][cb] = q4;
    __syncthreads();
    if (tid < C_HID) {
        float s = 0.f, q = 0.f;
#pragma unroll
        for (int g = 0; g < 8; g++) { s += rs[g][tid]; q += rq[g][tid]; }
        atomicAdd(&g_s1[tid], s);
        atomicAdd(&g_q1[tid], q);
    }
}

// ---- generic activation: x <- relu6(bn(x)), fp16, 8 halfs/thread ----
#define TA 256
__global__ void __launch_bounds__(TA) k_act(__half* __restrict__ x,
                                            const float* __restrict__ gg,
                                            const float* __restrict__ bb,
                                            const float* __restrict__ ss,
                                            const float* __restrict__ qq) {
    __shared__ float ssc[C_HID], ssh[C_HID];
    int tid = threadIdx.x;
    if (tid < C_HID) {
        float m = ss[tid] * (1.0f / N_PTS);
        float v = qq[tid] * (1.0f / N_PTS) - m * m;
        float sc = gg[tid] * rsqrtf(v + EPS);
        ssc[tid] = sc;
        ssh[tid] = bb[tid] - m * sc;
    }
    __syncthreads();

    size_t i = (size_t)blockIdx.x * TA + tid;        // uint4 = 8 halfs
    const size_t total = (size_t)N_PTS * C_HID / 8;  // 144/8=18 per row, aligned
    if (i < total) {
        int cb = (int)(i % 18) * 8;
        uint4 u = *(const uint4*)&x[i * 8];
        const __half2 zero2 = __floats2half2_rn(0.f, 0.f);
        const __half2 six2  = __floats2half2_rn(6.f, 6.f);
        unsigned int* up = &u.x;
        uint4 o;
        unsigned int* op = &o.x;
#pragma unroll
        for (int j = 0; j < 4; j++) {
            float2 f = __half22float2(*(__half2*)&up[j]);
            float v0 = fmaf(f.x, ssc[cb + 2 * j],     ssh[cb + 2 * j]);
            float v1 = fmaf(f.y, ssc[cb + 2 * j + 1], ssh[cb + 2 * j + 1]);
            __half2 h = __floats2half2_rn(v0, v1);
            h = __hmin2(__hmax2(h, zero2), six2);
            op[j] = *(unsigned int*)&h;
        }
        *(uint4*)&x[i * 8] = o;
    }
}

// ---- K3: pure weighted gather conv + BN2 stats ----
#define R3 64
#define T3 288
__global__ void __launch_bounds__(T3) k3_conv(const float* __restrict__ w2,
                                              const int* __restrict__ in_idx) {
    __shared__ int snbr[R3][KS];
    __shared__ __align__(8) float rs[4][C_HID], rq[4][C_HID];

    int tid = threadIdx.x;
    int row0 = blockIdx.x * R3;

    if (blockIdx.x == 0 && tid < C_OUT) { g_s3[tid] = 0.f; g_q3[tid] = 0.f; }

#pragma unroll
    for (int t = 0; t < 2; t++) {
        int i = tid + t * T3;
        int k = i / R3, r = i % R3;
        int rr = row0 + r;
        snbr[r][k] = (rr < N_PTS) ? in_idx[k * N_PTS + rr] : N_PTS;
    }
    __syncthreads();

    int cg = tid % 72, rl = tid / 72;
    int cb = cg * 2;

    float2 wk[KS];
#pragma unroll
    for (int k = 0; k < KS; k++) wk[k] = *(const float2*)&w2[k * C_HID + cb];

    float s0 = 0.f, s1 = 0.f, q0 = 0.f, q1 = 0.f;
#pragma unroll 2
    for (int j = 0; j < 16; j++) {
        int r = rl * 16 + j;
        unsigned int h[KS];
#pragma unroll
        for (int k = 0; k < KS; k++)
            h[k] = *(const unsigned int*)&g_x1h[snbr[r][k] * C_HID + cb];

        float a0 = 0.f, a1 = 0.f;
#pragma unroll
        for (int k = 0; k < KS; k++) {
            float2 x = __half22float2(*(__half2*)&h[k]);
            a0 = fmaf(wk[k].x, x.x, a0);
            a1 = fmaf(wk[k].y, x.y, a1);
        }
        int rr = row0 + r;
        if (rr < N_PTS) {
            __half2 hh = __floats2half2_rn(a0, a1);
            *(unsigned int*)&g_x2h[(size_t)rr * C_HID + cb] = *(unsigned int*)&hh;
            s0 += a0; q0 += a0 * a0;
            s1 += a1; q1 += a1 * a1;
        }
    }
    rs[rl][cb] = s0; rs[rl][cb + 1] = s1;
    rq[rl][cb] = q0; rq[rl][cb + 1] = q1;
    __syncthreads();
    if (tid < C_HID) {
        float s = rs[0][tid] + rs[1][tid] + rs[2][tid] + rs[3][tid];
        float q = rq[0][tid] + rq[1][tid] + rq[2][tid] + rq[3][tid];
        atomicAdd(&g_s2[tid], s);
        atomicAdd(&g_q2[tid], q);
    }
}

// ---- K5: y = x2_act @ w3 via mma.m16n8k16 + BN3 stats ----
#define T5 128
#define R5T 256
__global__ void __launch_bounds__(T5) k5_tc(const float* __restrict__ w3) {
    __shared__ __align__(4) unsigned int swp[72 * C_OUT];   // half2 (k,k+1) pairs
    __shared__ float ssum[C_OUT], ssq[C_OUT];

    int tid = threadIdx.x;
    int lane = tid & 31, wid = tid >> 5;
    int g = lane >> 2, c = lane & 3;

    for (int i = tid; i < 72 * C_OUT; i += T5) {
        int kk = i / C_OUT, n = i % C_OUT;
        __half2 h = __floats2half2_rn(w3[(2 * kk) * C_OUT + n],
                                      w3[(2 * kk + 1) * C_OUT + n]);
        swp[i] = *(unsigned int*)&h;
    }
    if (tid < C_OUT) { ssum[tid] = 0.f; ssq[tid] = 0.f; }
    __syncthreads();

    int row0 = blockIdx.x * R5T + wid * 64;

    float acc[4][3][4];
#pragma unroll
    for (int mt = 0; mt < 4; mt++)
#pragma unroll
        for (int nt = 0; nt < 3; nt++)
#pragma unroll
            for (int j = 0; j < 4; j++) acc[mt][nt][j] = 0.f;

#pragma unroll
    for (int ks = 0; ks < 9; ks++) {
        int k0 = ks * 16;
        unsigned int b[3][2];
        int kb = (k0 >> 1) + c;
#pragma unroll
        for (int nt = 0; nt < 3; nt++) {
            int n = nt * 8 + g;
            b[nt][0] = swp[kb * C_OUT + n];
            b[nt][1] = swp[(kb + 4) * C_OUT + n];
        }
#pragma unroll
        for (int mt = 0; mt < 4; mt++) {
            int r  = row0 + mt * 16 + g;
            int rA = min(r, N_PTS - 1);
            int rB = min(r + 8, N_PTS - 1);
            unsigned int a0 = *(const unsigned int*)&g_x2h[(size_t)rA * C_HID + k0 + 2 * c];
            unsigned int a1 = *(const unsigned int*)&g_x2h[(size_t)rB * C_HID + k0 + 2 * c];
            unsigned int a2 = *(const unsigned int*)&g_x2h[(size_t)rA * C_HID + k0 + 2 * c + 8];
            unsigned int a3 = *(const unsigned int*)&g_x2h[(size_t)rB * C_HID + k0 + 2 * c + 8];
#pragma unroll
            for (int nt = 0; nt < 3; nt++)
                mma16816(acc[mt][nt], a0, a1, a2, a3, b[nt][0], b[nt][1]);
        }
    }

    float s[3][2], q[3][2];
#pragma unroll
    for (int nt = 0; nt < 3; nt++) { s[nt][0] = s[nt][1] = 0.f; q[nt][0] = q[nt][1] = 0.f; }

#pragma unroll
    for (int mt = 0; mt < 4; mt++) {
        int r = row0 + mt * 16 + g;
#pragma unroll
        for (int nt = 0; nt < 3; nt++) {
            int n = nt * 8 + 2 * c;
            if (r < N_PTS) {
                float c0 = acc[mt][nt][0], c1 = acc[mt][nt][1];
                *(float2*)&g_y[(size_t)r * C_OUT + n] = make_float2(c0, c1);
                s[nt][0] += c0; q[nt][0] += c0 * c0;
                s[nt][1] += c1; q[nt][1] += c1 * c1;
            }
            if (r + 8 < N_PTS) {
                float c2 = acc[mt][nt][2], c3 = acc[mt][nt][3];
                *(float2*)&g_y[(size_t)(r + 8) * C_OUT + n] = make_float2(c2, c3);
                s[nt][0] += c2; q[nt][0] += c2 * c2;
                s[nt][1] += c3; q[nt][1] += c3 * c3;
            }
        }
    }
#pragma unroll
    for (int off = 16; off >= 4; off >>= 1) {
#pragma unroll
        for (int nt = 0; nt < 3; nt++) {
#pragma unroll
            for (int j = 0; j < 2; j++) {
                s[nt][j] += __shfl_down_sync(0xffffffffu, s[nt][j], off);
                q[nt][j] += __shfl_down_sync(0xffffffffu, q[nt][j], off);
            }
        }
    }
    if (g == 0) {
#pragma unroll
        for (int nt = 0; nt < 3; nt++) {
            int n = nt * 8 + 2 * c;
            atomicAdd(&ssum[n],     s[nt][0]);
            atomicAdd(&ssum[n + 1], s[nt][1]);
            atomicAdd(&ssq[n],      q[nt][0]);
            atomicAdd(&ssq[n + 1],  q[nt][1]);
        }
    }
    __syncthreads();
    if (tid < C_OUT) {
        atomicAdd(&g_s3[tid], ssum[tid]);
        atomicAdd(&g_q3[tid], ssq[tid]);
    }
}

// ---- K7: out = bn3(y) + feats (float4); block0 zeroes stage-1 accumulators ----
__global__ void k7_out(const float* __restrict__ feats, float* __restrict__ out,
                       const float* __restrict__ g3, const float* __restrict__ b3) {
    __shared__ float ssc[C_OUT], ssh[C_OUT];
    int tid = threadIdx.x;
    if (blockIdx.x == 0 && tid < C_HID) { g_s1[tid] = 0.f; g_q1[tid] = 0.f; }
    if (tid < C_OUT) {
        float m = g_s3[tid] * (1.0f / N_PTS);
        float v = g_q3[tid] * (1.0f / N_PTS) - m * m;
        float sc = g3[tid] * rsqrtf(v + EPS);
        ssc[tid] = sc;
        ssh[tid] = b3[tid] - m * sc;
    }
    __syncthreads();

    int i = blockIdx.x * blockDim.x + tid;   // float4 index
    if (i < N_PTS * C_OUT / 4) {
        int cb = (i % 6) * 4;
        float4 y  = *(const float4*)&g_y[i * 4];
        float4 f  = *(const float4*)&feats[i * 4];
        float4 o;
        o.x = fmaf(y.x, ssc[cb + 0], ssh[cb + 0]) + f.x;
        o.y = fmaf(y.y, ssc[cb + 1], ssh[cb + 1]) + f.y;
        o.z = fmaf(y.z, ssc[cb + 2], ssh[cb + 2]) + f.z;
        o.w = fmaf(y.w, ssc[cb + 3], ssh[cb + 3]) + f.w;
        *(float4*)&out[i * 4] = o;
    }
}

extern "C" void kernel_launch(void* const* d_in, const int* in_sizes, int n_in,
                              void* d_out, int out_size) {
    const float* feats = (const float*)d_in[0];
    const float* w1    = (const float*)d_in[1];
    const float* g1    = (const float*)d_in[2];
    const float* b1    = (const float*)d_in[3];
    const float* w2    = (const float*)d_in[4];
    const float* g2    = (const float*)d_in[5];
    const float* b2    = (const float*)d_in[6];
    const float* w3    = (const float*)d_in[7];
    const float* g3    = (const float*)d_in[8];
    const float* b3    = (const float*)d_in[9];
    const int*   in_idx = (const int*)d_in[10];
    float* out = (float*)d_out;

    __half *d_x1, *d_x2;
    float *d_s1, *d_q1, *d_s2, *d_q2;
    cudaGetSymbolAddress((void**)&d_x1, g_x1h);
    cudaGetSymbolAddress((void**)&d_x2, g_x2h);
    cudaGetSymbolAddress((void**)&d_s1, g_s1);
    cudaGetSymbolAddress((void**)&d_q1, g_q1);
    cudaGetSymbolAddress((void**)&d_s2, g_s2);
    cudaGetSymbolAddress((void**)&d_q2, g_q2);

    int nb1 = (N_PTS + R1 - 1) / R1;
    k1_gemm1<<<nb1, T1>>>(feats, w1);

    unsigned nba = (unsigned)(((size_t)N_PTS * C_HID / 8 + TA - 1) / TA);
    k_act<<<nba, TA>>>(d_x1, g1, b1, d_s1, d_q1);

    int nb3 = (N_PTS + R3 - 1) / R3;
    k3_conv<<<nb3, T3>>>(w2, in_idx);

    k_act<<<nba, TA>>>(d_x2, g2, b2, d_s2, d_q2);

    int nb5 = (N_PTS + R5T - 1) / R5T;
    k5_tc<<<nb5, T5>>>(w3);

    int total4 = N_PTS * C_OUT / 4;
    k7_out<<<(total4 + 255) / 256, 256>>>(feats, out, g3, b3);
}

// round 12
// speedup vs baseline: 1.1098x; 1.1098x over previous
#include <cuda_runtime.h>
#include <cuda_fp16.h>

#define N_PTS 100000
#define C_IN 24
#define C_HID 144
#define C_OUT 24
#define KS 9
#define EPS 1e-5f

// ---- scratch (device globals: allocation-free rule) ----
__device__ __align__(16) __half g_x1h[(N_PTS + 1) * C_HID];
__device__ __align__(16) __half g_x2h[N_PTS * C_HID];
__device__ __align__(16) float  g_y [N_PTS * C_OUT];

__device__ float g_s1[C_HID], g_q1[C_HID];
__device__ float g_s2[C_HID], g_q2[C_HID];
__device__ float g_s3[C_OUT], g_q3[C_OUT];

__device__ __forceinline__ float relu6f(float x) { return fminf(fmaxf(x, 0.f), 6.f); }

__device__ __forceinline__ void mma16816(float* d,
                                         unsigned a0, unsigned a1, unsigned a2, unsigned a3,
                                         unsigned b0, unsigned b1) {
    asm volatile("mma.sync.aligned.m16n8k16.row.col.f32.f16.f16.f32 "
                 "{%0,%1,%2,%3}, {%4,%5,%6,%7}, {%8,%9}, {%0,%1,%2,%3};\n"
                 : "+f"(d[0]), "+f"(d[1]), "+f"(d[2]), "+f"(d[3])
                 : "r"(a0), "r"(a1), "r"(a2), "r"(a3), "r"(b0), "r"(b1));
}

// ---- K1: x1 = feats @ w1 (fp16 out, fp32 stats); block0 zeroes stage-2 accums ----
#define R1 64
#define T1 288
__global__ void __launch_bounds__(T1) k1_gemm1(const float* __restrict__ feats,
                                               const float* __restrict__ w1) {
    __shared__ __align__(16) float sfT[C_IN][R1];
    __shared__ __align__(16) float sw1[C_IN * C_HID];
    __shared__ __align__(16) float rs[8][C_HID], rq[8][C_HID];

    int tid = threadIdx.x;
    int row0 = blockIdx.x * R1;

    if (blockIdx.x == 0 && tid < C_HID) { g_s2[tid] = 0.f; g_q2[tid] = 0.f; }

    for (int i = tid; i < C_IN * C_HID; i += T1) sw1[i] = w1[i];
    for (int i = tid; i < R1 * C_IN; i += T1) {
        int r = i / C_IN, k = i % C_IN;
        int rr = row0 + r;
        sfT[k][r] = (rr < N_PTS) ? feats[rr * C_IN + k] : 0.f;
    }
    __syncthreads();

    int c4 = tid % 36, rg = tid / 36;
    int cb = c4 * 4;
    float4 acc[8];
#pragma unroll
    for (int j = 0; j < 8; j++) acc[j] = make_float4(0.f, 0.f, 0.f, 0.f);

#pragma unroll
    for (int k = 0; k < C_IN; k++) {
        float4 w  = *(const float4*)&sw1[k * C_HID + cb];
        float4 xa = *(const float4*)&sfT[k][rg * 8];
        float4 xb = *(const float4*)&sfT[k][rg * 8 + 4];
        float xr[8] = {xa.x, xa.y, xa.z, xa.w, xb.x, xb.y, xb.z, xb.w};
#pragma unroll
        for (int j = 0; j < 8; j++) {
            acc[j].x = fmaf(w.x, xr[j], acc[j].x);
            acc[j].y = fmaf(w.y, xr[j], acc[j].y);
            acc[j].z = fmaf(w.z, xr[j], acc[j].z);
            acc[j].w = fmaf(w.w, xr[j], acc[j].w);
        }
    }

    float4 s4 = make_float4(0.f, 0.f, 0.f, 0.f), q4 = s4;
#pragma unroll
    for (int j = 0; j < 8; j++) {
        int rr = row0 + rg * 8 + j;
        if (rr < N_PTS) {
            __half2 h0 = __floats2half2_rn(acc[j].x, acc[j].y);
            __half2 h1 = __floats2half2_rn(acc[j].z, acc[j].w);
            uint2 pk;
            pk.x = *(unsigned int*)&h0;
            pk.y = *(unsigned int*)&h1;
            *(uint2*)&g_x1h[(size_t)rr * C_HID + cb] = pk;
        }
        s4.x += acc[j].x; s4.y += acc[j].y; s4.z += acc[j].z; s4.w += acc[j].w;
        q4.x += acc[j].x * acc[j].x; q4.y += acc[j].y * acc[j].y;
        q4.z += acc[j].z * acc[j].z; q4.w += acc[j].w * acc[j].w;
    }
    *(float4*)&rs[rg][cb] = s4;
    *(float4*)&rq[rg][cb] = q4;
    __syncthreads();
    if (tid < C_HID) {
        float s = 0.f, q = 0.f;
#pragma unroll
        for (int g = 0; g < 8; g++) { s += rs[g][tid]; q += rq[g][tid]; }
        atomicAdd(&g_s1[tid], s);
        atomicAdd(&g_q1[tid], q);
    }
}

// ---- K2: x1 <- relu6(bn1(x1)), fp16, 8 halfs/thread, vector LDS ----
#define TA 256
__global__ void __launch_bounds__(TA) k2_act(const float* __restrict__ gg,
                                             const float* __restrict__ bb) {
    __shared__ __align__(16) float ssc[C_HID], ssh[C_HID];
    int tid = threadIdx.x;
    if (tid < C_HID) {
        float m = g_s1[tid] * (1.0f / N_PTS);
        float v = g_q1[tid] * (1.0f / N_PTS) - m * m;
        float sc = gg[tid] * rsqrtf(v + EPS);
        ssc[tid] = sc;
        ssh[tid] = bb[tid] - m * sc;
    }
    __syncthreads();

    size_t i = (size_t)blockIdx.x * TA + tid;        // uint4 = 8 halfs
    const size_t total = (size_t)N_PTS * C_HID / 8;  // 144/8=18 per row, aligned
    if (i < total) {
        int cb = (int)(i % 18) * 8;
        uint4 u = *(const uint4*)&g_x1h[i * 8];
        float4 scA = *(const float4*)&ssc[cb];
        float4 scB = *(const float4*)&ssc[cb + 4];
        float4 shA = *(const float4*)&ssh[cb];
        float4 shB = *(const float4*)&ssh[cb + 4];
        float scr[8] = {scA.x, scA.y, scA.z, scA.w, scB.x, scB.y, scB.z, scB.w};
        float shr[8] = {shA.x, shA.y, shA.z, shA.w, shB.x, shB.y, shB.z, shB.w};
        unsigned int* up = &u.x;
        uint4 o;
        unsigned int* op = &o.x;
#pragma unroll
        for (int j = 0; j < 4; j++) {
            float2 f = __half22float2(*(__half2*)&up[j]);
            float v0 = relu6f(fmaf(f.x, scr[2 * j],     shr[2 * j]));
            float v1 = relu6f(fmaf(f.y, scr[2 * j + 1], shr[2 * j + 1]));
            __half2 h = __floats2half2_rn(v0, v1);
            op[j] = *(unsigned int*)&h;
        }
        *(uint4*)&g_x1h[i * 8] = o;
    }
}

// ---- K3: pure weighted gather conv + BN2 stats (x2 stored RAW fp16) ----
#define R3 64
#define T3 288
__global__ void __launch_bounds__(T3) k3_conv(const float* __restrict__ w2,
                                              const int* __restrict__ in_idx) {
    __shared__ int snbr[R3][KS];
    __shared__ __align__(8) float rs[4][C_HID], rq[4][C_HID];

    int tid = threadIdx.x;
    int row0 = blockIdx.x * R3;

    if (blockIdx.x == 0 && tid < C_OUT) { g_s3[tid] = 0.f; g_q3[tid] = 0.f; }

#pragma unroll
    for (int t = 0; t < 2; t++) {
        int i = tid + t * T3;
        int k = i / R3, r = i % R3;
        int rr = row0 + r;
        snbr[r][k] = (rr < N_PTS) ? in_idx[k * N_PTS + rr] : N_PTS;
    }
    __syncthreads();

    int cg = tid % 72, rl = tid / 72;
    int cb = cg * 2;

    float2 wk[KS];
#pragma unroll
    for (int k = 0; k < KS; k++) wk[k] = *(const float2*)&w2[k * C_HID + cb];

    float s0 = 0.f, s1 = 0.f, q0 = 0.f, q1 = 0.f;
#pragma unroll 2
    for (int j = 0; j < 16; j++) {
        int r = rl * 16 + j;
        unsigned int h[KS];
#pragma unroll
        for (int k = 0; k < KS; k++)
            h[k] = *(const unsigned int*)&g_x1h[snbr[r][k] * C_HID + cb];

        float a0 = 0.f, a1 = 0.f;
#pragma unroll
        for (int k = 0; k < KS; k++) {
            float2 x = __half22float2(*(__half2*)&h[k]);
            a0 = fmaf(wk[k].x, x.x, a0);
            a1 = fmaf(wk[k].y, x.y, a1);
        }
        int rr = row0 + r;
        if (rr < N_PTS) {
            __half2 hh = __floats2half2_rn(a0, a1);
            *(unsigned int*)&g_x2h[(size_t)rr * C_HID + cb] = *(unsigned int*)&hh;
            s0 += a0; q0 += a0 * a0;
            s1 += a1; q1 += a1 * a1;
        }
    }
    rs[rl][cb] = s0; rs[rl][cb + 1] = s1;
    rq[rl][cb] = q0; rq[rl][cb + 1] = q1;
    __syncthreads();
    if (tid < C_HID) {
        float s = rs[0][tid] + rs[1][tid] + rs[2][tid] + rs[3][tid];
        float q = rq[0][tid] + rq[1][tid] + rq[2][tid] + rq[3][tid];
        atomicAdd(&g_s2[tid], s);
        atomicAdd(&g_q2[tid], q);
    }
}

// ---- K5: y = relu6(bn2(x2)) @ w3 via mma.m16n8k16, activation fused per fragment ----
#define T5 128
#define R5T 256
__global__ void __launch_bounds__(T5) k5_tc(const float* __restrict__ w3,
                                            const float* __restrict__ g2,
                                            const float* __restrict__ b2) {
    __shared__ __align__(4) unsigned int swp[72 * C_OUT];   // half2 (k,k+1) pairs
    __shared__ __align__(8) float ssc[C_HID], ssh[C_HID];
    __shared__ float ssum[C_OUT], ssq[C_OUT];

    int tid = threadIdx.x;
    int lane = tid & 31, wid = tid >> 5;
    int g = lane >> 2, c = lane & 3;

    for (int i = tid; i < 72 * C_OUT; i += T5) {
        int kk = i / C_OUT, n = i % C_OUT;
        __half2 h = __floats2half2_rn(w3[(2 * kk) * C_OUT + n],
                                      w3[(2 * kk + 1) * C_OUT + n]);
        swp[i] = *(unsigned int*)&h;
    }
    // NOTE: strided — T5 (128) < C_HID (144); the R11 bug was `if (tid < C_HID)`.
    for (int i = tid; i < C_HID; i += T5) {
        float m = g_s2[i] * (1.0f / N_PTS);
        float v = g_q2[i] * (1.0f / N_PTS) - m * m;
        float sc = g2[i] * rsqrtf(v + EPS);
        ssc[i] = sc;
        ssh[i] = b2[i] - m * sc;
    }
    if (tid < C_OUT) { ssum[tid] = 0.f; ssq[tid] = 0.f; }
    __syncthreads();

    int row0 = blockIdx.x * R5T + wid * 64;

    float acc[4][3][4];
#pragma unroll
    for (int mt = 0; mt < 4; mt++)
#pragma unroll
        for (int nt = 0; nt < 3; nt++)
#pragma unroll
            for (int j = 0; j < 4; j++) acc[mt][nt][j] = 0.f;

#pragma unroll
    for (int ks = 0; ks < 9; ks++) {
        int k0 = ks * 16;
        unsigned int b[3][2];
        int kb = (k0 >> 1) + c;
#pragma unroll
        for (int nt = 0; nt < 3; nt++) {
            int n = nt * 8 + g;
            b[nt][0] = swp[kb * C_OUT + n];
            b[nt][1] = swp[(kb + 4) * C_OUT + n];
        }
        int chL = k0 + 2 * c;          // fragment cols (lo pair)
        int chH = chL + 8;             // fragment cols (hi pair)
        float2 scL = *(const float2*)&ssc[chL];
        float2 shL = *(const float2*)&ssh[chL];
        float2 scH = *(const float2*)&ssc[chH];
        float2 shH = *(const float2*)&ssh[chH];
#pragma unroll
        for (int mt = 0; mt < 4; mt++) {
            int r  = row0 + mt * 16 + g;
            int rA = min(r, N_PTS - 1);
            int rB = min(r + 8, N_PTS - 1);
            unsigned int a0 = *(const unsigned int*)&g_x2h[(size_t)rA * C_HID + chL];
            unsigned int a1 = *(const unsigned int*)&g_x2h[(size_t)rB * C_HID + chL];
            unsigned int a2 = *(const unsigned int*)&g_x2h[(size_t)rA * C_HID + chH];
            unsigned int a3 = *(const unsigned int*)&g_x2h[(size_t)rB * C_HID + chH];
            // fused bn2 + relu6 (fp32 math, each element touched exactly once)
            float2 f;
            __half2 h;
            f = __half22float2(*(__half2*)&a0);
            h = __floats2half2_rn(relu6f(fmaf(f.x, scL.x, shL.x)),
                                  relu6f(fmaf(f.y, scL.y, shL.y)));
            a0 = *(unsigned int*)&h;
            f = __half22float2(*(__half2*)&a1);
            h = __floats2half2_rn(relu6f(fmaf(f.x, scL.x, shL.x)),
                                  relu6f(fmaf(f.y, scL.y, shL.y)));
            a1 = *(unsigned int*)&h;
            f = __half22float2(*(__half2*)&a2);
            h = __floats2half2_rn(relu6f(fmaf(f.x, scH.x, shH.x)),
                                  relu6f(fmaf(f.y, scH.y, shH.y)));
            a2 = *(unsigned int*)&h;
            f = __half22float2(*(__half2*)&a3);
            h = __floats2half2_rn(relu6f(fmaf(f.x, scH.x, shH.x)),
                                  relu6f(fmaf(f.y, scH.y, shH.y)));
            a3 = *(unsigned int*)&h;
#pragma unroll
            for (int nt = 0; nt < 3; nt++)
                mma16816(acc[mt][nt], a0, a1, a2, a3, b[nt][0], b[nt][1]);
        }
    }

    float s[3][2], q[3][2];
#pragma unroll
    for (int nt = 0; nt < 3; nt++) { s[nt][0] = s[nt][1] = 0.f; q[nt][0] = q[nt][1] = 0.f; }

#pragma unroll
    for (int mt = 0; mt < 4; mt++) {
        int r = row0 + mt * 16 + g;
#pragma unroll
        for (int nt = 0; nt < 3; nt++) {
            int n = nt * 8 + 2 * c;
            if (r < N_PTS) {
                float c0 = acc[mt][nt][0], c1 = acc[mt][nt][1];
                *(float2*)&g_y[(size_t)r * C_OUT + n] = make_float2(c0, c1);
                s[nt][0] += c0; q[nt][0] += c0 * c0;
                s[nt][1] += c1; q[nt][1] += c1 * c1;
            }
            if (r + 8 < N_PTS) {
                float c2 = acc[mt][nt][2], c3 = acc[mt][nt][3];
                *(float2*)&g_y[(size_t)(r + 8) * C_OUT + n] = make_float2(c2, c3);
                s[nt][0] += c2; q[nt][0] += c2 * c2;
                s[nt][1] += c3; q[nt][1] += c3 * c3;
            }
        }
    }
#pragma unroll
    for (int off = 16; off >= 4; off >>= 1) {
#pragma unroll
        for (int nt = 0; nt < 3; nt++) {
#pragma unroll
            for (int j = 0; j < 2; j++) {
                s[nt][j] += __shfl_down_sync(0xffffffffu, s[nt][j], off);
                q[nt][j] += __shfl_down_sync(0xffffffffu, q[nt][j], off);
            }
        }
    }
    if (g == 0) {
#pragma unroll
        for (int nt = 0; nt < 3; nt++) {
            int n = nt * 8 + 2 * c;
            atomicAdd(&ssum[n],     s[nt][0]);
            atomicAdd(&ssum[n + 1], s[nt][1]);
            atomicAdd(&ssq[n],      q[nt][0]);
            atomicAdd(&ssq[n + 1],  q[nt][1]);
        }
    }
    __syncthreads();
    if (tid < C_OUT) {
        atomicAdd(&g_s3[tid], ssum[tid]);
        atomicAdd(&g_q3[tid], ssq[tid]);
    }
}

// ---- K7: out = bn3(y) + feats (float4); block0 zeroes stage-1 accumulators ----
__global__ void k7_out(const float* __restrict__ feats, float* __restrict__ out,
                       const float* __restrict__ g3, const float* __restrict__ b3) {
    __shared__ float ssc[C_OUT], ssh[C_OUT];
    int tid = threadIdx.x;
    if (blockIdx.x == 0 && tid < C_HID) { g_s1[tid] = 0.f; g_q1[tid] = 0.f; }
    if (tid < C_OUT) {
        float m = g_s3[tid] * (1.0f / N_PTS);
        float v = g_q3[tid] * (1.0f / N_PTS) - m * m;
        float sc = g3[tid] * rsqrtf(v + EPS);
        ssc[tid] = sc;
        ssh[tid] = b3[tid] - m * sc;
    }
    __syncthreads();

    int i = blockIdx.x * blockDim.x + tid;   // float4 index
    if (i < N_PTS * C_OUT / 4) {
        int cb = (i % 6) * 4;
        float4 y  = *(const float4*)&g_y[i * 4];
        float4 f  = *(const float4*)&feats[i * 4];
        float4 o;
        o.x = fmaf(y.x, ssc[cb + 0], ssh[cb + 0]) + f.x;
        o.y = fmaf(y.y, ssc[cb + 1], ssh[cb + 1]) + f.y;
        o.z = fmaf(y.z, ssc[cb + 2], ssh[cb + 2]) + f.z;
        o.w = fmaf(y.w, ssc[cb + 3], ssh[cb + 3]) + f.w;
        *(float4*)&out[i * 4] = o;
    }
}

extern "C" void kernel_launch(void* const* d_in, const int* in_sizes, int n_in,
                              void* d_out, int out_size) {
    const float* feats = (const float*)d_in[0];
    const float* w1    = (const float*)d_in[1];
    const float* g1    = (const float*)d_in[2];
    const float* b1    = (const float*)d_in[3];
    const float* w2    = (const float*)d_in[4];
    const float* g2    = (const float*)d_in[5];
    const float* b2    = (const float*)d_in[6];
    const float* w3    = (const float*)d_in[7];
    const float* g3    = (const float*)d_in[8];
    const float* b3    = (const float*)d_in[9];
    const int*   in_idx = (const int*)d_in[10];
    float* out = (float*)d_out;

    int nb1 = (N_PTS + R1 - 1) / R1;
    k1_gemm1<<<nb1, T1>>>(feats, w1);

    unsigned nba = (unsigned)(((size_t)N_PTS * C_HID / 8 + TA - 1) / TA);
    k2_act<<<nba, TA>>>(g1, b1);

    int nb3 = (N_PTS + R3 - 1) / R3;
    k3_conv<<<nb3, T3>>>(w2, in_idx);

    int nb5 = (N_PTS + R5T - 1) / R5T;
    k5_tc<<<nb5, T5>>>(w3, g2, b2);

    int total4 = N_PTS * C_OUT / 4;
    k7_out<<<(total4 + 255) / 256, 256>>>(feats, out, g3, b3);
}